// round 1
// baseline (speedup 1.0000x reference)
#include <cuda_runtime.h>
#include <math.h>

#define DM 1024
#define NH 16
#define HD 64
#define NB 2
#define SQ 2048
#define MTOT (NB*SQ)   // 4096

// ---------------- scratch (static device globals; no allocation) ----------------
__device__ float  g_tw[4][DM*DM];     // ternarized weights, fp32 {-1,0,1}: wq,wk,wv,wo
__device__ float  g_qb[MTOT*DM];
__device__ float  g_kb[MTOT*DM];
__device__ float  g_vb[MTOT*DM];
__device__ float  g_ab[MTOT*DM];
__device__ double g_part[4][32];
__device__ float  g_thr[4];

// ---------------- abs-mean threshold (deterministic 2-stage) ----------------
__global__ void absmean_partial(const float* __restrict__ w0, const float* __restrict__ w1,
                                const float* __restrict__ w2, const float* __restrict__ w3) {
    int mid = blockIdx.x >> 5;      // 0..3
    int blk = blockIdx.x & 31;      // 0..31
    const float* w = (mid == 0) ? w0 : (mid == 1) ? w1 : (mid == 2) ? w2 : w3;
    const int chunk = (DM * DM) / 32;  // 32768
    const float* p = w + blk * chunk;
    double acc = 0.0;
    for (int i = threadIdx.x; i < chunk; i += blockDim.x)
        acc += (double)fabsf(p[i]);
    __shared__ double sred[256];
    sred[threadIdx.x] = acc;
    __syncthreads();
    for (int s = 128; s > 0; s >>= 1) {
        if (threadIdx.x < s) sred[threadIdx.x] += sred[threadIdx.x + s];
        __syncthreads();
    }
    if (threadIdx.x == 0) g_part[mid][blk] = sred[0];
}

__global__ void absmean_final() {
    int mid = threadIdx.x;
    if (mid < 4) {
        double s = 0.0;
        for (int i = 0; i < 32; i++) s += g_part[mid][i];
        g_thr[mid] = (float)(s / (double)(DM * DM));
    }
}

__global__ void ternarize_k(const float* __restrict__ w0, const float* __restrict__ w1,
                            const float* __restrict__ w2, const float* __restrict__ w3) {
    int idx = blockIdx.x * blockDim.x + threadIdx.x;     // 0 .. 4M-1
    int mid = idx >> 20;
    int off = idx & ((1 << 20) - 1);
    const float* w = (mid == 0) ? w0 : (mid == 1) ? w1 : (mid == 2) ? w2 : w3;
    float t = g_thr[mid];
    float x = w[off];
    g_tw[mid][off] = (fabsf(x) > t) ? (x > 0.f ? 1.f : -1.f) : 0.f;
}

// ---------------- SGEMM: C[M,1024] = A[M,1024] @ W^T, W row-major [1024,1024] ----------------
// BM=128, BN=64, BK=16, 256 threads, 8x4 micro-tile per thread.
__global__ __launch_bounds__(256) void gemm_xwt(const float* __restrict__ A,
                                                const float* __restrict__ W,
                                                float* __restrict__ C) {
    __shared__ float As[16][132];  // [k][m], padded (132*4 % 16 == 0)
    __shared__ float Bs[16][68];   // [k][n], padded (68*4 % 16 == 0)
    const int tid = threadIdx.x;
    const int tx = tid & 15;       // 0..15 -> cols tx*4..+3
    const int ty = tid >> 4;       // 0..15 -> rows ty*8..+7
    const int row0 = blockIdx.y * 128;
    const int col0 = blockIdx.x * 64;
    const int lm = tid >> 2;       // 0..63
    const int kf = (tid & 3) * 4;  // 0,4,8,12

    float acc[8][4];
#pragma unroll
    for (int i = 0; i < 8; i++)
#pragma unroll
        for (int j = 0; j < 4; j++) acc[i][j] = 0.f;

    for (int k0 = 0; k0 < DM; k0 += 16) {
        float4 a0 = *(const float4*)&A[(size_t)(row0 + lm) * DM + k0 + kf];
        float4 a1 = *(const float4*)&A[(size_t)(row0 + lm + 64) * DM + k0 + kf];
        float4 b0 = *(const float4*)&W[(size_t)(col0 + lm) * DM + k0 + kf];
        As[kf + 0][lm] = a0.x; As[kf + 1][lm] = a0.y; As[kf + 2][lm] = a0.z; As[kf + 3][lm] = a0.w;
        As[kf + 0][lm + 64] = a1.x; As[kf + 1][lm + 64] = a1.y; As[kf + 2][lm + 64] = a1.z; As[kf + 3][lm + 64] = a1.w;
        Bs[kf + 0][lm] = b0.x; Bs[kf + 1][lm] = b0.y; Bs[kf + 2][lm] = b0.z; Bs[kf + 3][lm] = b0.w;
        __syncthreads();
#pragma unroll
        for (int kk = 0; kk < 16; kk++) {
            float4 av0 = *(const float4*)&As[kk][ty * 8];
            float4 av1 = *(const float4*)&As[kk][ty * 8 + 4];
            float4 bv  = *(const float4*)&Bs[kk][tx * 4];
            float am[8] = {av0.x, av0.y, av0.z, av0.w, av1.x, av1.y, av1.z, av1.w};
            float bn[4] = {bv.x, bv.y, bv.z, bv.w};
#pragma unroll
            for (int i = 0; i < 8; i++)
#pragma unroll
                for (int j = 0; j < 4; j++) acc[i][j] += am[i] * bn[j];
        }
        __syncthreads();
    }
#pragma unroll
    for (int i = 0; i < 8; i++) {
        float4 o = make_float4(acc[i][0], acc[i][1], acc[i][2], acc[i][3]);
        *(float4*)&C[(size_t)(row0 + ty * 8 + i) * DM + col0 + tx * 4] = o;
    }
}

// ---------------- flash attention (fp32, online softmax) ----------------
// Block: 256 threads handle a 64-row q tile for one (b,h). Keys streamed in 64-wide tiles.
// Thread (ty,tx): S rows ty*4..+3, S cols (keys) tx*4..+3; O rows ty*4..+3, d-cols tx*4..+3.
__global__ __launch_bounds__(256) void flash_attn() {
    extern __shared__ float sm[];
    float* Qst = sm;                // [64 d][68]  (q along row)
    float* Kst = sm + 64 * 68;      // [64 d][68]  (key along row)
    float* Vs  = sm + 2 * 64 * 68;  // [64 key][68] (d along row)
    float* Pt  = sm + 3 * 64 * 68;  // [64 key][68] (q along row)
    const int b = blockIdx.z, h = blockIdx.y, q0 = blockIdx.x * 64;
    const int tid = threadIdx.x;
    const int tx = tid & 15, ty = tid >> 4;
    const float scale = 0.125f;     // 1/sqrt(64), exact power of 2

    // Stage Q transposed (Qst[d][q]) with scale folded in.
    for (int i = tid; i < 64 * 64; i += 256) {
        int d = i & 63, q = i >> 6;
        Qst[d * 68 + q] = g_qb[(size_t)(b * SQ + q0 + q) * DM + h * HD + d] * scale;
    }

    float m[4], l[4], O[4][4];
#pragma unroll
    for (int i = 0; i < 4; i++) {
        m[i] = -1e30f; l[i] = 0.f;
#pragma unroll
        for (int j = 0; j < 4; j++) O[i][j] = 0.f;
    }
    __syncthreads();

    for (int kt = 0; kt < SQ; kt += 64) {
        // load K (transposed) and V tiles, both coalesced on the fast dim
        for (int i = tid; i < 64 * 64; i += 256) {
            int c = i & 63, r = i >> 6;  // c = d (K) / d-col (V), r = key
            Kst[c * 68 + r] = g_kb[(size_t)(b * SQ + kt + r) * DM + h * HD + c];
            Vs[r * 68 + c]  = g_vb[(size_t)(b * SQ + kt + r) * DM + h * HD + c];
        }
        __syncthreads();

        // S = Q K^T (64x64x64)
        float s[4][4];
#pragma unroll
        for (int i = 0; i < 4; i++)
#pragma unroll
            for (int j = 0; j < 4; j++) s[i][j] = 0.f;
#pragma unroll 4
        for (int d = 0; d < 64; d++) {
            float4 q4 = *(const float4*)&Qst[d * 68 + ty * 4];
            float4 k4 = *(const float4*)&Kst[d * 68 + tx * 4];
            float qa[4] = {q4.x, q4.y, q4.z, q4.w};
            float kb[4] = {k4.x, k4.y, k4.z, k4.w};
#pragma unroll
            for (int i = 0; i < 4; i++)
#pragma unroll
                for (int j = 0; j < 4; j++) s[i][j] += qa[i] * kb[j];
        }

        // online softmax; rows are shared across the 16 tx-threads (same ty => same 16-lane segment)
#pragma unroll
        for (int i = 0; i < 4; i++) {
            float mloc = fmaxf(fmaxf(s[i][0], s[i][1]), fmaxf(s[i][2], s[i][3]));
#pragma unroll
            for (int off = 8; off >= 1; off >>= 1)
                mloc = fmaxf(mloc, __shfl_xor_sync(0xffffffffu, mloc, off, 16));
            float mnew = fmaxf(m[i], mloc);
            float alpha = __expf(m[i] - mnew);
            float ls = 0.f;
#pragma unroll
            for (int j = 0; j < 4; j++) { s[i][j] = __expf(s[i][j] - mnew); ls += s[i][j]; }
#pragma unroll
            for (int off = 8; off >= 1; off >>= 1)
                ls += __shfl_xor_sync(0xffffffffu, ls, off, 16);
            l[i] = l[i] * alpha + ls;
            m[i] = mnew;
#pragma unroll
            for (int j = 0; j < 4; j++) O[i][j] *= alpha;
#pragma unroll
            for (int j = 0; j < 4; j++) Pt[(tx * 4 + j) * 68 + ty * 4 + i] = s[i][j];
        }
        __syncthreads();

        // O += P V (64x64x64)
#pragma unroll 4
        for (int kk = 0; kk < 64; kk++) {
            float4 p4 = *(const float4*)&Pt[kk * 68 + ty * 4];
            float4 v4 = *(const float4*)&Vs[kk * 68 + tx * 4];
            float pa[4] = {p4.x, p4.y, p4.z, p4.w};
            float vb[4] = {v4.x, v4.y, v4.z, v4.w};
#pragma unroll
            for (int i = 0; i < 4; i++)
#pragma unroll
                for (int j = 0; j < 4; j++) O[i][j] += pa[i] * vb[j];
        }
        __syncthreads();
    }

#pragma unroll
    for (int i = 0; i < 4; i++) {
        float inv = 1.f / l[i];
        float4 o = make_float4(O[i][0] * inv, O[i][1] * inv, O[i][2] * inv, O[i][3] * inv);
        *(float4*)&g_ab[(size_t)(b * SQ + q0 + ty * 4 + i) * DM + h * HD + tx * 4] = o;
    }
}

// ---------------- launcher ----------------
extern "C" void kernel_launch(void* const* d_in, const int* in_sizes, int n_in,
                              void* d_out, int out_size) {
    (void)in_sizes; (void)n_in; (void)out_size;
    const float* query = (const float*)d_in[0];
    const float* key   = (const float*)d_in[1];
    const float* value = (const float*)d_in[2];
    const float* wq    = (const float*)d_in[3];
    const float* wk    = (const float*)d_in[4];
    const float* wv    = (const float*)d_in[5];
    const float* wo    = (const float*)d_in[6];
    float* out = (float*)d_out;

    float *pq, *pk, *pv, *pa, *ptw;
    cudaGetSymbolAddress((void**)&pq,  g_qb);
    cudaGetSymbolAddress((void**)&pk,  g_kb);
    cudaGetSymbolAddress((void**)&pv,  g_vb);
    cudaGetSymbolAddress((void**)&pa,  g_ab);
    cudaGetSymbolAddress((void**)&ptw, g_tw);

    const int smem_flash = 4 * 64 * 68 * 4;  // 69632 B
    cudaFuncSetAttribute(flash_attn, cudaFuncAttributeMaxDynamicSharedMemorySize, smem_flash);

    absmean_partial<<<128, 256>>>(wq, wk, wv, wo);
    absmean_final<<<1, 4>>>();
    ternarize_k<<<(4 * DM * DM) / 256, 256>>>(wq, wk, wv, wo);

    dim3 gg(DM / 64, MTOT / 128);  // (16, 32)
    gemm_xwt<<<gg, 256>>>(query, ptw + 0 * DM * DM, pq);
    gemm_xwt<<<gg, 256>>>(key,   ptw + 1 * DM * DM, pk);
    gemm_xwt<<<gg, 256>>>(value, ptw + 2 * DM * DM, pv);

    flash_attn<<<dim3(SQ / 64, NH, NB), 256, smem_flash>>>();

    gemm_xwt<<<gg, 256>>>(pa, ptw + 3 * DM * DM, out);
}

// round 5
// speedup vs baseline: 2.0116x; 2.0116x over previous
#include <cuda_runtime.h>
#include <cuda_bf16.h>
#include <cstdint>
#include <math.h>

#define DM 1024
#define NH 16
#define HD 64
#define NB 2
#define SQ 2048
#define MTOT (NB*SQ)   // 4096

// ================= mma.sync helpers (sm_80-era, family-portable PTX) =================
__device__ __forceinline__ uint32_t smem_u32(const void* p) {
    uint32_t a;
    asm("{ .reg .u64 t; cvta.to.shared.u64 t, %1; cvt.u32.u64 %0, t; }" : "=r"(a) : "l"(p));
    return a;
}
__device__ __forceinline__ void ldm_x4(uint32_t* r, uint32_t addr) {
    asm volatile("ldmatrix.sync.aligned.m8n8.x4.shared.b16 {%0,%1,%2,%3}, [%4];"
                 : "=r"(r[0]), "=r"(r[1]), "=r"(r[2]), "=r"(r[3]) : "r"(addr));
}
__device__ __forceinline__ void mma_bf16(float* d, const uint32_t* a, const uint32_t* b) {
    asm volatile("mma.sync.aligned.m16n8k16.row.col.f32.bf16.bf16.f32 "
                 "{%0,%1,%2,%3}, {%4,%5,%6,%7}, {%8,%9}, {%0,%1,%2,%3};"
                 : "+f"(d[0]), "+f"(d[1]), "+f"(d[2]), "+f"(d[3])
                 : "r"(a[0]), "r"(a[1]), "r"(a[2]), "r"(a[3]), "r"(b[0]), "r"(b[1]));
}
__device__ __forceinline__ void mma_tf32(float* d, const uint32_t* a, const uint32_t* b) {
    asm volatile("mma.sync.aligned.m16n8k8.row.col.f32.tf32.tf32.f32 "
                 "{%0,%1,%2,%3}, {%4,%5,%6,%7}, {%8,%9}, {%0,%1,%2,%3};"
                 : "+f"(d[0]), "+f"(d[1]), "+f"(d[2]), "+f"(d[3])
                 : "r"(a[0]), "r"(a[1]), "r"(a[2]), "r"(a[3]), "r"(b[0]), "r"(b[1]));
}
__device__ __forceinline__ uint32_t cvt_tf32(float x) {
    uint32_t r; asm("cvt.rna.tf32.f32 %0, %1;" : "=r"(r) : "f"(x)); return r;
}
__device__ __forceinline__ void cp_async16(uint32_t saddr, const void* gaddr) {
    asm volatile("cp.async.cg.shared.global [%0], [%1], 16;" :: "r"(saddr), "l"(gaddr));
}
#define CP_COMMIT() asm volatile("cp.async.commit_group;")
#define CP_WAIT1()  asm volatile("cp.async.wait_group 1;")
#define SW128(off) ((off) ^ (((off) >> 3) & 0x70))
__device__ __forceinline__ uint32_t pack_bf16x2(float x, float y) {
    __nv_bfloat162 t = __floats2bfloat162_rn(x, y);
    return *(uint32_t*)&t;
}

// ================= scratch =================
__device__ __nv_bfloat16 g_twb[4][DM*DM];     // ternary weights bf16 {-1,0,1}
__device__ __nv_bfloat16 g_split[MTOT*3*DM];  // limb-augmented activations
__device__ float  g_qb[MTOT*DM];
__device__ float  g_kb[MTOT*DM];
__device__ float  g_vb[MTOT*DM];
__device__ float  g_ab[MTOT*DM];
__device__ double g_part[4][32];
__device__ float  g_thr[4];

// ================= abs-mean + ternarize =================
__global__ void absmean_partial(const float* __restrict__ w0, const float* __restrict__ w1,
                                const float* __restrict__ w2, const float* __restrict__ w3) {
    int mid = blockIdx.x >> 5, blk = blockIdx.x & 31;
    const float* w = (mid == 0) ? w0 : (mid == 1) ? w1 : (mid == 2) ? w2 : w3;
    const int chunk = (DM * DM) / 32;
    const float* p = w + blk * chunk;
    double acc = 0.0;
    for (int i = threadIdx.x; i < chunk; i += blockDim.x) acc += (double)fabsf(p[i]);
    __shared__ double sred[256];
    sred[threadIdx.x] = acc;
    __syncthreads();
    for (int s = 128; s > 0; s >>= 1) {
        if (threadIdx.x < s) sred[threadIdx.x] += sred[threadIdx.x + s];
        __syncthreads();
    }
    if (threadIdx.x == 0) g_part[mid][blk] = sred[0];
}
__global__ void absmean_final() {
    int mid = threadIdx.x;
    if (mid < 4) {
        double s = 0.0;
        for (int i = 0; i < 32; i++) s += g_part[mid][i];
        g_thr[mid] = (float)(s / (double)(DM * DM));
    }
}
__global__ void ternarize_k(const float* __restrict__ w0, const float* __restrict__ w1,
                            const float* __restrict__ w2, const float* __restrict__ w3) {
    int idx = blockIdx.x * blockDim.x + threadIdx.x;
    int mid = idx >> 20, off = idx & ((1 << 20) - 1);
    const float* w = (mid == 0) ? w0 : (mid == 1) ? w1 : (mid == 2) ? w2 : w3;
    float t = g_thr[mid];
    float x = w[off];
    float v = (fabsf(x) > t) ? (x > 0.f ? 1.f : -1.f) : 0.f;
    g_twb[mid][off] = __float2bfloat16(v);
}

// ================= activation limb splits =================
__device__ __forceinline__ void store_bf4(__nv_bfloat16* dst, float a, float b, float c, float d) {
    __nv_bfloat162* p = (__nv_bfloat162*)dst;
    p[0] = __floats2bfloat162_rn(a, b);
    p[1] = __floats2bfloat162_rn(c, d);
}
__global__ void split3_k(const float* __restrict__ X) {
    int i = blockIdx.x * blockDim.x + threadIdx.x;   // float4 index
    int m = i >> 8, j = (i & 255) * 4;
    float4 x = ((const float4*)X)[i];
    float h0 = __bfloat162float(__float2bfloat16(x.x));
    float h1 = __bfloat162float(__float2bfloat16(x.y));
    float h2 = __bfloat162float(__float2bfloat16(x.z));
    float h3 = __bfloat162float(__float2bfloat16(x.w));
    float r0 = x.x - h0, r1 = x.y - h1, r2 = x.z - h2, r3 = x.w - h3;
    float m0 = __bfloat162float(__float2bfloat16(r0));
    float m1 = __bfloat162float(__float2bfloat16(r1));
    float m2 = __bfloat162float(__float2bfloat16(r2));
    float m3 = __bfloat162float(__float2bfloat16(r3));
    __nv_bfloat16* base = g_split + (size_t)m * 3072;
    store_bf4(base + j, h0, h1, h2, h3);
    store_bf4(base + 1024 + j, m0, m1, m2, m3);
    store_bf4(base + 2048 + j, r0 - m0, r1 - m1, r2 - m2, r3 - m3);
}
__global__ void split2_k(const float* __restrict__ X) {
    int i = blockIdx.x * blockDim.x + threadIdx.x;
    int m = i >> 8, j = (i & 255) * 4;
    float4 x = ((const float4*)X)[i];
    float h0 = __bfloat162float(__float2bfloat16(x.x));
    float h1 = __bfloat162float(__float2bfloat16(x.y));
    float h2 = __bfloat162float(__float2bfloat16(x.z));
    float h3 = __bfloat162float(__float2bfloat16(x.w));
    __nv_bfloat16* base = g_split + (size_t)m * 2048;
    store_bf4(base + j, h0, h1, h2, h3);
    store_bf4(base + 1024 + j, x.x - h0, x.y - h1, x.z - h2, x.w - h3);
}

// ================= mma.sync GEMM: C[M,1024] = A[M,KA] @ W^T (weight col = k mod 1024) ===
// CTA 128x128, BK=64, 256 threads (8 warps: 2m x 4n, warp tile 64x32), 2-stage cp.async.
__global__ __launch_bounds__(256, 2) void gemm_mma(const __nv_bfloat16* __restrict__ A,
                                                   const __nv_bfloat16* __restrict__ W,
                                                   float* __restrict__ C, int KA) {
    extern __shared__ char smraw[];
    const int tid = threadIdx.x, lane = tid & 31, wid = tid >> 5;
    const int wm = (wid >> 2) * 64, wn = (wid & 3) * 32;
    const int row0 = blockIdx.y * 128, col0 = blockIdx.x * 128;
    const uint32_t sbase = smem_u32(smraw);

    float acc[4][4][4];
#pragma unroll
    for (int i = 0; i < 4; i++)
#pragma unroll
        for (int j = 0; j < 4; j++)
#pragma unroll
            for (int k = 0; k < 4; k++) acc[i][j][k] = 0.f;

    auto issue_load = [&](int it) {
        const int stage = it & 1;
        const int k0 = it * 64;
        const int bcol = k0 & 1023;
        const uint32_t sa = sbase + stage * 32768u;
        const uint32_t sb = sa + 16384u;
#pragma unroll
        for (int j = 0; j < 4; j++) {
            int c = tid * 4 + j;          // 0..1023
            int r = c >> 3, g = c & 7;
            cp_async16(sa + SW128(r * 128 + g * 16), A + (size_t)(row0 + r) * KA + k0 + g * 8);
            cp_async16(sb + SW128(r * 128 + g * 16), W + (size_t)(col0 + r) * 1024 + bcol + g * 8);
        }
        CP_COMMIT();
    };

    const int NIT = KA >> 6;
    issue_load(0);
    issue_load(1);

    for (int it = 0; it < NIT; it++) {
        CP_WAIT1();
        __syncthreads();
        const uint32_t sa = sbase + (it & 1) * 32768u;
        const uint32_t sb = sa + 16384u;
#pragma unroll
        for (int ks = 0; ks < 4; ks++) {
            uint32_t a[4][4];
#pragma unroll
            for (int mi = 0; mi < 4; mi++)
                ldm_x4(a[mi], sa + SW128((wm + mi * 16 + (lane & 15)) * 128 +
                                         (2 * ks + (lane >> 4)) * 16));
            uint32_t b[2][4];
#pragma unroll
            for (int p = 0; p < 2; p++)
                ldm_x4(b[p], sb + SW128((wn + p * 16 + ((lane >> 4) << 3) + (lane & 7)) * 128 +
                                        (2 * ks + ((lane >> 3) & 1)) * 16));
#pragma unroll
            for (int mi = 0; mi < 4; mi++)
#pragma unroll
                for (int ni = 0; ni < 4; ni++)
                    mma_bf16(acc[mi][ni], a[mi], &b[ni >> 1][(ni & 1) * 2]);
        }
        __syncthreads();
        if (it + 2 < NIT) issue_load(it + 2);
    }

    // epilogue: direct stores (float2)
#pragma unroll
    for (int mi = 0; mi < 4; mi++) {
#pragma unroll
        for (int ni = 0; ni < 4; ni++) {
            int r = row0 + wm + mi * 16 + (lane >> 2);
            int c = col0 + wn + ni * 8 + 2 * (lane & 3);
            *(float2*)&C[(size_t)r * DM + c] = make_float2(acc[mi][ni][0], acc[mi][ni][1]);
            *(float2*)&C[(size_t)(r + 8) * DM + c] = make_float2(acc[mi][ni][2], acc[mi][ni][3]);
        }
    }
}

// ================= flash attention on mma.sync =================
// 128 threads (4 warps), q-tile 64 (warp w: rows 16w..16w+15), k-tiles of 64.
// QK^T: tf32 2-limb x 3 passes (3xTF32, fp32-grade). PV: bf16 2-limb P & V, 3 passes.
__global__ __launch_bounds__(128) void flash_mma() {
    extern __shared__ char smraw[];
    float* Qs  = (float*)smraw;          // [64][68] fp32 (scaled)
    float* Ks  = Qs + 64 * 68;           // [64][68] fp32
    float* Vst = Ks + 64 * 68;           // [64][68] fp32 staging
    __nv_bfloat16* Vthi = (__nv_bfloat16*)(Vst + 64 * 68);  // [64 d][72 key]
    __nv_bfloat16* Vtlo = Vthi + 64 * 72;
    const uint32_t uQs = smem_u32(Qs), uKs = smem_u32(Ks);
    const uint32_t uVthi = smem_u32(Vthi), uVtlo = smem_u32(Vtlo);

    const int b = blockIdx.z, h = blockIdx.y, q0 = blockIdx.x * 64;
    const int tid = threadIdx.x, lane = tid & 31, wid = tid >> 5;
    const int g = lane >> 2, tig = lane & 3;
    const int qbase = wid * 16;

    const float* Qg = g_qb + (size_t)(b * SQ + q0) * DM + h * HD;
    const float* Kg = g_kb + (size_t)(b * SQ) * DM + h * HD;
    const float* Vg = g_vb + (size_t)(b * SQ) * DM + h * HD;

    // stage Q (scaled by 1/8)
    for (int i = tid; i < 64 * 16; i += 128) {
        int r = i >> 4, c4 = (i & 15) * 4;
        float4 v = *(const float4*)(Qg + (size_t)r * DM + c4);
        float4 s = make_float4(v.x * 0.125f, v.y * 0.125f, v.z * 0.125f, v.w * 0.125f);
        *(float4*)&Qs[r * 68 + c4] = s;
    }

    float o[8][4];
#pragma unroll
    for (int n = 0; n < 8; n++)
#pragma unroll
        for (int k = 0; k < 4; k++) o[n][k] = 0.f;
    float m0 = -1e30f, m1 = -1e30f, l0 = 0.f, l1 = 0.f;

    for (int kt = 0; kt < SQ; kt += 64) {
        // load K, V tiles (fp32, coalesced)
        for (int i = tid; i < 64 * 16; i += 128) {
            int r = i >> 4, c4 = (i & 15) * 4;
            *(float4*)&Ks[r * 68 + c4]  = *(const float4*)(Kg + (size_t)(kt + r) * DM + c4);
            *(float4*)&Vst[r * 68 + c4] = *(const float4*)(Vg + (size_t)(kt + r) * DM + c4);
        }
        __syncthreads();
        // transpose V into bf16 limbs Vt[d][key], conflict-free 8d x 4kp lane tiling
        for (int t = 0; t < 16; t++) {
            int tile = (tid >> 5) + 4 * t;              // 0..63
            int d  = ((tile & 7) << 3) + (lane & 7);
            int kp = ((tile >> 3) << 2) + (lane >> 3);
            float v0 = Vst[(2 * kp) * 68 + d];
            float v1 = Vst[(2 * kp + 1) * 68 + d];
            __nv_bfloat16 h0 = __float2bfloat16(v0), h1 = __float2bfloat16(v1);
            float r0f = v0 - __bfloat162float(h0), r1f = v1 - __bfloat162float(h1);
            *(__nv_bfloat162*)&Vthi[d * 72 + 2 * kp] = __halves2bfloat162(h0, h1);
            *(__nv_bfloat162*)&Vtlo[d * 72 + 2 * kp] = __floats2bfloat162_rn(r0f, r1f);
        }
        __syncthreads();

        // ---- S = Q K^T  (3xTF32) ----
        float sf[8][4];
#pragma unroll
        for (int n = 0; n < 8; n++)
#pragma unroll
            for (int k = 0; k < 4; k++) sf[n][k] = 0.f;
#pragma unroll
        for (int ks = 0; ks < 8; ks++) {
            uint32_t ahi[4], alo[4];
#pragma unroll
            for (int idx = 0; idx < 4; idx++) {
                int r = qbase + g + 8 * (idx & 1);
                int d = ks * 8 + tig + 4 * (idx >> 1);
                float v = Qs[r * 68 + d];
                ahi[idx] = cvt_tf32(v);
                alo[idx] = cvt_tf32(v - __uint_as_float(ahi[idx]));
            }
#pragma unroll
            for (int n = 0; n < 8; n++) {
                int key = n * 8 + g;
                float v0 = Ks[key * 68 + ks * 8 + tig];
                float v1 = Ks[key * 68 + ks * 8 + tig + 4];
                uint32_t bhi[2], blo[2];
                bhi[0] = cvt_tf32(v0); blo[0] = cvt_tf32(v0 - __uint_as_float(bhi[0]));
                bhi[1] = cvt_tf32(v1); blo[1] = cvt_tf32(v1 - __uint_as_float(bhi[1]));
                mma_tf32(sf[n], ahi, bhi);
                mma_tf32(sf[n], ahi, blo);
                mma_tf32(sf[n], alo, bhi);
            }
        }

        // ---- online softmax on C-fragments (rows g and g+8) ----
        float mx0 = -1e30f, mx1 = -1e30f;
#pragma unroll
        for (int n = 0; n < 8; n++) {
            mx0 = fmaxf(mx0, fmaxf(sf[n][0], sf[n][1]));
            mx1 = fmaxf(mx1, fmaxf(sf[n][2], sf[n][3]));
        }
        mx0 = fmaxf(mx0, __shfl_xor_sync(0xffffffffu, mx0, 1));
        mx0 = fmaxf(mx0, __shfl_xor_sync(0xffffffffu, mx0, 2));
        mx1 = fmaxf(mx1, __shfl_xor_sync(0xffffffffu, mx1, 1));
        mx1 = fmaxf(mx1, __shfl_xor_sync(0xffffffffu, mx1, 2));
        float mn0 = fmaxf(m0, mx0), mn1 = fmaxf(m1, mx1);
        float al0 = __expf(m0 - mn0), al1 = __expf(m1 - mn1);
        float ls0 = 0.f, ls1 = 0.f;
#pragma unroll
        for (int n = 0; n < 8; n++) {
            sf[n][0] = __expf(sf[n][0] - mn0); ls0 += sf[n][0];
            sf[n][1] = __expf(sf[n][1] - mn0); ls0 += sf[n][1];
            sf[n][2] = __expf(sf[n][2] - mn1); ls1 += sf[n][2];
            sf[n][3] = __expf(sf[n][3] - mn1); ls1 += sf[n][3];
        }
        ls0 += __shfl_xor_sync(0xffffffffu, ls0, 1);
        ls0 += __shfl_xor_sync(0xffffffffu, ls0, 2);
        ls1 += __shfl_xor_sync(0xffffffffu, ls1, 1);
        ls1 += __shfl_xor_sync(0xffffffffu, ls1, 2);
        l0 = l0 * al0 + ls0; m0 = mn0;
        l1 = l1 * al1 + ls1; m1 = mn1;
#pragma unroll
        for (int n = 0; n < 8; n++) {
            o[n][0] *= al0; o[n][1] *= al0; o[n][2] *= al1; o[n][3] *= al1;
        }

        // ---- O += P V  (bf16, 2-limb P x 2-limb V, 3 passes) ----
#pragma unroll
        for (int j = 0; j < 4; j++) {
            // P A-frags directly from S C-frags (identity layout)
            float p00 = sf[2 * j][0], p01 = sf[2 * j][1];
            float p10 = sf[2 * j][2], p11 = sf[2 * j][3];
            float p20 = sf[2 * j + 1][0], p21 = sf[2 * j + 1][1];
            float p30 = sf[2 * j + 1][2], p31 = sf[2 * j + 1][3];
            uint32_t ahi[4], alo[4];
            ahi[0] = pack_bf16x2(p00, p01);
            ahi[1] = pack_bf16x2(p10, p11);
            ahi[2] = pack_bf16x2(p20, p21);
            ahi[3] = pack_bf16x2(p30, p31);
            alo[0] = pack_bf16x2(p00 - __bfloat162float(__float2bfloat16(p00)),
                                 p01 - __bfloat162float(__float2bfloat16(p01)));
            alo[1] = pack_bf16x2(p10 - __bfloat162float(__float2bfloat16(p10)),
                                 p11 - __bfloat162float(__float2bfloat16(p11)));
            alo[2] = pack_bf16x2(p20 - __bfloat162float(__float2bfloat16(p20)),
                                 p21 - __bfloat162float(__float2bfloat16(p21)));
            alo[3] = pack_bf16x2(p30 - __bfloat162float(__float2bfloat16(p30)),
                                 p31 - __bfloat162float(__float2bfloat16(p31)));
#pragma unroll
            for (int n = 0; n < 8; n++) {
                int drow = n * 8 + g;
                uint32_t bhi[2], blo[2];
                bhi[0] = *(const uint32_t*)&Vthi[drow * 72 + j * 16 + 2 * tig];
                bhi[1] = *(const uint32_t*)&Vthi[drow * 72 + j * 16 + 8 + 2 * tig];
                blo[0] = *(const uint32_t*)&Vtlo[drow * 72 + j * 16 + 2 * tig];
                blo[1] = *(const uint32_t*)&Vtlo[drow * 72 + j * 16 + 8 + 2 * tig];
                mma_bf16(o[n], ahi, bhi);
                mma_bf16(o[n], alo, bhi);
                mma_bf16(o[n], ahi, blo);
            }
        }
        __syncthreads();
    }

    float inv0 = 1.f / l0, inv1 = 1.f / l1;
    float* Og = g_ab + (size_t)(b * SQ + q0 + qbase) * DM + h * HD;
#pragma unroll
    for (int n = 0; n < 8; n++) {
        int c = n * 8 + 2 * tig;
        *(float2*)(Og + (size_t)g * DM + c) = make_float2(o[n][0] * inv0, o[n][1] * inv0);
        *(float2*)(Og + (size_t)(g + 8) * DM + c) = make_float2(o[n][2] * inv1, o[n][3] * inv1);
    }
    (void)uQs; (void)uKs; (void)uVthi; (void)uVtlo;
}

// ================= launcher =================
extern "C" void kernel_launch(void* const* d_in, const int* in_sizes, int n_in,
                              void* d_out, int out_size) {
    (void)in_sizes; (void)n_in; (void)out_size;
    const float* query = (const float*)d_in[0];
    const float* key   = (const float*)d_in[1];
    const float* value = (const float*)d_in[2];
    const float* wq    = (const float*)d_in[3];
    const float* wk    = (const float*)d_in[4];
    const float* wv    = (const float*)d_in[5];
    const float* wo    = (const float*)d_in[6];
    float* out = (float*)d_out;

    float *pq, *pk, *pv, *pa;
    __nv_bfloat16 *ptw, *psp;
    cudaGetSymbolAddress((void**)&pq,  g_qb);
    cudaGetSymbolAddress((void**)&pk,  g_kb);
    cudaGetSymbolAddress((void**)&pv,  g_vb);
    cudaGetSymbolAddress((void**)&pa,  g_ab);
    cudaGetSymbolAddress((void**)&ptw, g_twb);
    cudaGetSymbolAddress((void**)&psp, g_split);

    const int smem_gemm  = 65536;                       // 2 stages x (16KB A + 16KB B)
    const int smem_flash = 3 * 64 * 68 * 4 + 2 * 64 * 72 * 2;  // 70656
    cudaFuncSetAttribute(gemm_mma,  cudaFuncAttributeMaxDynamicSharedMemorySize, smem_gemm);
    cudaFuncSetAttribute(flash_mma, cudaFuncAttributeMaxDynamicSharedMemorySize, smem_flash);

    absmean_partial<<<128, 256>>>(wq, wk, wv, wo);
    absmean_final<<<1, 4>>>();
    ternarize_k<<<(4 * DM * DM) / 256, 256>>>(wq, wk, wv, wo);

    dim3 gg(DM / 128, MTOT / 128);   // (8, 32)
    const int nf4 = MTOT * DM / 4;

    split3_k<<<nf4 / 256, 256>>>(query);
    gemm_mma<<<gg, 256, smem_gemm>>>(psp, ptw + 0 * (size_t)DM * DM, pq, 3072);
    split3_k<<<nf4 / 256, 256>>>(key);
    gemm_mma<<<gg, 256, smem_gemm>>>(psp, ptw + 1 * (size_t)DM * DM, pk, 3072);
    split2_k<<<nf4 / 256, 256>>>(value);
    gemm_mma<<<gg, 256, smem_gemm>>>(psp, ptw + 2 * (size_t)DM * DM, pv, 2048);

    flash_mma<<<dim3(SQ / 64, NH, NB), 128, smem_flash>>>();

    split2_k<<<nf4 / 256, 256>>>(pa);
    gemm_mma<<<gg, 256, smem_gemm>>>(psp, ptw + 3 * (size_t)DM * DM, out, 2048);
}

// round 6
// speedup vs baseline: 2.4911x; 1.2384x over previous
#include <cuda_runtime.h>
#include <cuda_bf16.h>
#include <cstdint>
#include <math.h>

#define DM 1024
#define NH 16
#define HD 64
#define NB 2
#define SQ 2048
#define MTOT (NB*SQ)   // 4096

// ================= mma.sync helpers (sm_80-era, family-portable PTX) =================
__device__ __forceinline__ uint32_t smem_u32(const void* p) {
    uint32_t a;
    asm("{ .reg .u64 t; cvta.to.shared.u64 t, %1; cvt.u32.u64 %0, t; }" : "=r"(a) : "l"(p));
    return a;
}
__device__ __forceinline__ void ldm_x4(uint32_t* r, uint32_t addr) {
    asm volatile("ldmatrix.sync.aligned.m8n8.x4.shared.b16 {%0,%1,%2,%3}, [%4];"
                 : "=r"(r[0]), "=r"(r[1]), "=r"(r[2]), "=r"(r[3]) : "r"(addr));
}
__device__ __forceinline__ void mma_bf16(float* d, const uint32_t* a, const uint32_t* b) {
    asm volatile("mma.sync.aligned.m16n8k16.row.col.f32.bf16.bf16.f32 "
                 "{%0,%1,%2,%3}, {%4,%5,%6,%7}, {%8,%9}, {%0,%1,%2,%3};"
                 : "+f"(d[0]), "+f"(d[1]), "+f"(d[2]), "+f"(d[3])
                 : "r"(a[0]), "r"(a[1]), "r"(a[2]), "r"(a[3]), "r"(b[0]), "r"(b[1]));
}
__device__ __forceinline__ void mma_tf32(float* d, const uint32_t* a, const uint32_t* b) {
    asm volatile("mma.sync.aligned.m16n8k8.row.col.f32.tf32.tf32.f32 "
                 "{%0,%1,%2,%3}, {%4,%5,%6,%7}, {%8,%9}, {%0,%1,%2,%3};"
                 : "+f"(d[0]), "+f"(d[1]), "+f"(d[2]), "+f"(d[3])
                 : "r"(a[0]), "r"(a[1]), "r"(a[2]), "r"(a[3]), "r"(b[0]), "r"(b[1]));
}
__device__ __forceinline__ uint32_t cvt_tf32(float x) {
    uint32_t r; asm("cvt.rna.tf32.f32 %0, %1;" : "=r"(r) : "f"(x)); return r;
}
__device__ __forceinline__ void cp_async16(uint32_t saddr, const void* gaddr) {
    asm volatile("cp.async.cg.shared.global [%0], [%1], 16;" :: "r"(saddr), "l"(gaddr));
}
#define CP_COMMIT() asm volatile("cp.async.commit_group;")
#define CP_WAIT1()  asm volatile("cp.async.wait_group 1;")
#define CP_WAIT0()  asm volatile("cp.async.wait_group 0;")
#define SW128(off) ((off) ^ (((off) >> 3) & 0x70))
__device__ __forceinline__ uint32_t pack_bf16x2(float x, float y) {
    __nv_bfloat162 t = __floats2bfloat162_rn(x, y);
    return *(uint32_t*)&t;
}

// ================= scratch =================
__device__ __nv_bfloat16 g_twb[4][DM*DM];     // ternary weights bf16 {-1,0,1}
__device__ __nv_bfloat16 g_split[MTOT*3*DM];  // limb-augmented activations
__device__ float  g_qb[MTOT*DM];
__device__ float  g_kb[MTOT*DM];
__device__ float  g_vb[MTOT*DM];
__device__ float  g_ab[MTOT*DM];
__device__ double g_part[4][32];
__device__ float  g_thr[4];
// fragment-layout precomputed operands for flash attention
__device__ uint32_t g_qfhi[512*8192];   // [b*16+qt][h] tiles of 8192: [ks8][w8][lane32][r4]
__device__ uint32_t g_qflo[512*8192];
__device__ uint32_t g_kfhi[1024*4096];  // [(b*16+h)*32+kt] tiles of 4096: [ks8][n8][lane32][r2]
__device__ uint32_t g_kflo[1024*4096];
__device__ uint32_t g_vfhi[1024*2048];  // [(b*16+h)*32+kt] tiles of 2048: [j4][n8][lane32][r2]
__device__ uint32_t g_vflo[1024*2048];

// ================= abs-mean + ternarize =================
__global__ void absmean_partial(const float* __restrict__ w0, const float* __restrict__ w1,
                                const float* __restrict__ w2, const float* __restrict__ w3) {
    int mid = blockIdx.x >> 5, blk = blockIdx.x & 31;
    const float* w = (mid == 0) ? w0 : (mid == 1) ? w1 : (mid == 2) ? w2 : w3;
    const int chunk = (DM * DM) / 32;
    const float* p = w + blk * chunk;
    double acc = 0.0;
    for (int i = threadIdx.x; i < chunk; i += blockDim.x) acc += (double)fabsf(p[i]);
    __shared__ double sred[256];
    sred[threadIdx.x] = acc;
    __syncthreads();
    for (int s = 128; s > 0; s >>= 1) {
        if (threadIdx.x < s) sred[threadIdx.x] += sred[threadIdx.x + s];
        __syncthreads();
    }
    if (threadIdx.x == 0) g_part[mid][blk] = sred[0];
}
__global__ void absmean_final() {
    int mid = threadIdx.x;
    if (mid < 4) {
        double s = 0.0;
        for (int i = 0; i < 32; i++) s += g_part[mid][i];
        g_thr[mid] = (float)(s / (double)(DM * DM));
    }
}
__global__ void ternarize_k(const float* __restrict__ w0, const float* __restrict__ w1,
                            const float* __restrict__ w2, const float* __restrict__ w3) {
    int idx = blockIdx.x * blockDim.x + threadIdx.x;
    int mid = idx >> 20, off = idx & ((1 << 20) - 1);
    const float* w = (mid == 0) ? w0 : (mid == 1) ? w1 : (mid == 2) ? w2 : w3;
    float t = g_thr[mid];
    float x = w[off];
    float v = (fabsf(x) > t) ? (x > 0.f ? 1.f : -1.f) : 0.f;
    g_twb[mid][off] = __float2bfloat16(v);
}

// ================= activation limb splits =================
__device__ __forceinline__ void store_bf4(__nv_bfloat16* dst, float a, float b, float c, float d) {
    __nv_bfloat162* p = (__nv_bfloat162*)dst;
    p[0] = __floats2bfloat162_rn(a, b);
    p[1] = __floats2bfloat162_rn(c, d);
}
__global__ void split3_k(const float* __restrict__ X) {
    int i = blockIdx.x * blockDim.x + threadIdx.x;
    int m = i >> 8, j = (i & 255) * 4;
    float4 x = ((const float4*)X)[i];
    float h0 = __bfloat162float(__float2bfloat16(x.x));
    float h1 = __bfloat162float(__float2bfloat16(x.y));
    float h2 = __bfloat162float(__float2bfloat16(x.z));
    float h3 = __bfloat162float(__float2bfloat16(x.w));
    float r0 = x.x - h0, r1 = x.y - h1, r2 = x.z - h2, r3 = x.w - h3;
    float m0 = __bfloat162float(__float2bfloat16(r0));
    float m1 = __bfloat162float(__float2bfloat16(r1));
    float m2 = __bfloat162float(__float2bfloat16(r2));
    float m3 = __bfloat162float(__float2bfloat16(r3));
    __nv_bfloat16* base = g_split + (size_t)m * 3072;
    store_bf4(base + j, h0, h1, h2, h3);
    store_bf4(base + 1024 + j, m0, m1, m2, m3);
    store_bf4(base + 2048 + j, r0 - m0, r1 - m1, r2 - m2, r3 - m3);
}
__global__ void split2_k(const float* __restrict__ X) {
    int i = blockIdx.x * blockDim.x + threadIdx.x;
    int m = i >> 8, j = (i & 255) * 4;
    float4 x = ((const float4*)X)[i];
    float h0 = __bfloat162float(__float2bfloat16(x.x));
    float h1 = __bfloat162float(__float2bfloat16(x.y));
    float h2 = __bfloat162float(__float2bfloat16(x.z));
    float h3 = __bfloat162float(__float2bfloat16(x.w));
    __nv_bfloat16* base = g_split + (size_t)m * 2048;
    store_bf4(base + j, h0, h1, h2, h3);
    store_bf4(base + 1024 + j, x.x - h0, x.y - h1, x.z - h2, x.w - h3);
}

// ================= mma.sync GEMM (unchanged from R5) =================
__global__ __launch_bounds__(256, 2) void gemm_mma(const __nv_bfloat16* __restrict__ A,
                                                   const __nv_bfloat16* __restrict__ W,
                                                   float* __restrict__ C, int KA) {
    extern __shared__ char smraw[];
    const int tid = threadIdx.x, lane = tid & 31, wid = tid >> 5;
    const int wm = (wid >> 2) * 64, wn = (wid & 3) * 32;
    const int row0 = blockIdx.y * 128, col0 = blockIdx.x * 128;
    const uint32_t sbase = smem_u32(smraw);

    float acc[4][4][4];
#pragma unroll
    for (int i = 0; i < 4; i++)
#pragma unroll
        for (int j = 0; j < 4; j++)
#pragma unroll
            for (int k = 0; k < 4; k++) acc[i][j][k] = 0.f;

    auto issue_load = [&](int it) {
        const int stage = it & 1;
        const int k0 = it * 64;
        const int bcol = k0 & 1023;
        const uint32_t sa = sbase + stage * 32768u;
        const uint32_t sb = sa + 16384u;
#pragma unroll
        for (int j = 0; j < 4; j++) {
            int c = tid * 4 + j;
            int r = c >> 3, g = c & 7;
            cp_async16(sa + SW128(r * 128 + g * 16), A + (size_t)(row0 + r) * KA + k0 + g * 8);
            cp_async16(sb + SW128(r * 128 + g * 16), W + (size_t)(col0 + r) * 1024 + bcol + g * 8);
        }
        CP_COMMIT();
    };

    const int NIT = KA >> 6;
    issue_load(0);
    issue_load(1);

    for (int it = 0; it < NIT; it++) {
        CP_WAIT1();
        __syncthreads();
        const uint32_t sa = sbase + (it & 1) * 32768u;
        const uint32_t sb = sa + 16384u;
#pragma unroll
        for (int ks = 0; ks < 4; ks++) {
            uint32_t a[4][4];
#pragma unroll
            for (int mi = 0; mi < 4; mi++)
                ldm_x4(a[mi], sa + SW128((wm + mi * 16 + (lane & 15)) * 128 +
                                         (2 * ks + (lane >> 4)) * 16));
            uint32_t b[2][4];
#pragma unroll
            for (int p = 0; p < 2; p++)
                ldm_x4(b[p], sb + SW128((wn + p * 16 + ((lane >> 4) << 3) + (lane & 7)) * 128 +
                                        (2 * ks + ((lane >> 3) & 1)) * 16));
#pragma unroll
            for (int mi = 0; mi < 4; mi++)
#pragma unroll
                for (int ni = 0; ni < 4; ni++)
                    mma_bf16(acc[mi][ni], a[mi], &b[ni >> 1][(ni & 1) * 2]);
        }
        __syncthreads();
        if (it + 2 < NIT) issue_load(it + 2);
    }

#pragma unroll
    for (int mi = 0; mi < 4; mi++) {
#pragma unroll
        for (int ni = 0; ni < 4; ni++) {
            int r = row0 + wm + mi * 16 + (lane >> 2);
            int c = col0 + wn + ni * 8 + 2 * (lane & 3);
            *(float2*)&C[(size_t)r * DM + c] = make_float2(acc[mi][ni][0], acc[mi][ni][1]);
            *(float2*)&C[(size_t)(r + 8) * DM + c] = make_float2(acc[mi][ni][2], acc[mi][ni][3]);
        }
    }
}

// ================= fragment writers (one-shot conversion into mma register layout) ====
// Q: tile per (b, qt, h): [128 q][64 d] -> 8192 regs: [ks8][w8][lane32][r4], tf32 limbs, x0.125
__global__ __launch_bounds__(256) void qf_writer() {
    __shared__ float tile[128 * 65];
    const int qt = blockIdx.x, h = blockIdx.y, b = blockIdx.z;
    const int tid = threadIdx.x;
    for (int idx = tid; idx < 128 * 64; idx += 256) {
        int row = idx >> 6, col = idx & 63;
        tile[row * 65 + col] = g_qb[(size_t)(b * SQ + qt * 128 + row) * DM + h * HD + col];
    }
    __syncthreads();
    size_t base = (size_t)((b * 16 + qt) * 16 + h) * 8192;
    for (int t2 = tid; t2 < 8192; t2 += 256) {
        int r = t2 & 3, lane = (t2 >> 2) & 31, w = (t2 >> 7) & 7, ks = (t2 >> 10) & 7;
        int g = lane >> 2, tig = lane & 3;
        int row = w * 16 + g + 8 * (r & 1);
        int col = ks * 8 + tig + 4 * (r >> 1);
        float v = tile[row * 65 + col] * 0.125f;
        uint32_t hi = cvt_tf32(v);
        g_qfhi[base + t2] = hi;
        g_qflo[base + t2] = cvt_tf32(v - __uint_as_float(hi));
    }
}
// K: tile per (b, h, kt): [64 key][64 d] -> 4096 regs: [ks8][n8][lane32][r2], tf32 limbs
__global__ __launch_bounds__(256) void kf_writer() {
    __shared__ float tile[64 * 65];
    const int kt = blockIdx.x, h = blockIdx.y, b = blockIdx.z;
    const int tid = threadIdx.x;
    for (int idx = tid; idx < 64 * 64; idx += 256) {
        int row = idx >> 6, col = idx & 63;
        tile[row * 65 + col] = g_kb[(size_t)(b * SQ + kt * 64 + row) * DM + h * HD + col];
    }
    __syncthreads();
    size_t base = (size_t)((b * 16 + h) * 32 + kt) * 4096;
    for (int t2 = tid; t2 < 4096; t2 += 256) {
        int r = t2 & 1, lane = (t2 >> 1) & 31, n = (t2 >> 6) & 7, ks = (t2 >> 9) & 7;
        int g = lane >> 2, tig = lane & 3;
        int key = n * 8 + g;
        int d = ks * 8 + tig + 4 * r;
        float v = tile[key * 65 + d];
        uint32_t hi = cvt_tf32(v);
        g_kfhi[base + t2] = hi;
        g_kflo[base + t2] = cvt_tf32(v - __uint_as_float(hi));
    }
}
// V: tile per (b, h, kt): [64 key][64 d] -> 2048 regs: [j4][n8][lane32][r2], bf16x2 limbs
__global__ __launch_bounds__(256) void vf_writer() {
    __shared__ float tile[64 * 65];
    const int kt = blockIdx.x, h = blockIdx.y, b = blockIdx.z;
    const int tid = threadIdx.x;
    for (int idx = tid; idx < 64 * 64; idx += 256) {
        int row = idx >> 6, col = idx & 63;
        tile[row * 65 + col] = g_vb[(size_t)(b * SQ + kt * 64 + row) * DM + h * HD + col];
    }
    __syncthreads();
    size_t base = (size_t)((b * 16 + h) * 32 + kt) * 2048;
    for (int t2 = tid; t2 < 2048; t2 += 256) {
        int r = t2 & 1, lane = (t2 >> 1) & 31, n = (t2 >> 6) & 7, j = (t2 >> 9) & 3;
        int g = lane >> 2, tig = lane & 3;
        int key0 = j * 16 + 2 * tig + 8 * r;
        int d = n * 8 + g;
        float v0 = tile[key0 * 65 + d];
        float v1 = tile[(key0 + 1) * 65 + d];
        float h0 = __bfloat162float(__float2bfloat16(v0));
        float h1 = __bfloat162float(__float2bfloat16(v1));
        g_vfhi[base + t2] = pack_bf16x2(v0, v1);
        g_vflo[base + t2] = pack_bf16x2(v0 - h0, v1 - h1);
    }
}

// ================= flash attention: pure LDS -> HMMA pipeline ======================
// 256 threads (8 warps), q-tile 128 (warp w: rows w*16..+15), k-tiles of 64.
// SMEM: Qfhi 32KB | Qflo 32KB | 2 stages x (Kfhi 16K, Kflo 16K, Vfhi 8K, Vflo 8K)
#define FOFF_QHI 0u
#define FOFF_QLO 32768u
#define FOFF_ST  65536u
#define FSTAGE   49152u
#define FOFF_KHI 0u
#define FOFF_KLO 16384u
#define FOFF_VHI 32768u
#define FOFF_VLO 40960u
__global__ __launch_bounds__(256) void flash_mma2() {
    extern __shared__ char smraw[];
    const uint32_t sbase = smem_u32(smraw);
    const int qt = blockIdx.x, h = blockIdx.y, b = blockIdx.z;
    const int tid = threadIdx.x, lane = tid & 31, wid = tid >> 5;
    const int g = lane >> 2, tig = lane & 3;

    const uint32_t* Qhi = g_qfhi + (size_t)((b * 16 + qt) * 16 + h) * 8192;
    const uint32_t* Qlo = g_qflo + (size_t)((b * 16 + qt) * 16 + h) * 8192;
    const uint32_t* Khi = g_kfhi + (size_t)((b * 16 + h) * 32) * 4096;
    const uint32_t* Klo = g_kflo + (size_t)((b * 16 + h) * 32) * 4096;
    const uint32_t* Vhi = g_vfhi + (size_t)((b * 16 + h) * 32) * 2048;
    const uint32_t* Vlo = g_vflo + (size_t)((b * 16 + h) * 32) * 2048;

    // Q fragments resident in SMEM (one shot)
#pragma unroll
    for (int i = 0; i < 8; i++) {
        int idx = tid + i * 256;                 // 0..2047 (16B units)
        cp_async16(sbase + FOFF_QHI + idx * 16, Qhi + idx * 4);
        cp_async16(sbase + FOFF_QLO + idx * 16, Qlo + idx * 4);
    }
    CP_COMMIT();

    auto issue_stage = [&](int t) {
        const uint32_t st = sbase + FOFF_ST + (t & 1) * FSTAGE;
        const uint32_t* kh = Khi + (size_t)t * 4096;
        const uint32_t* kl = Klo + (size_t)t * 4096;
        const uint32_t* vh = Vhi + (size_t)t * 2048;
        const uint32_t* vl = Vlo + (size_t)t * 2048;
#pragma unroll
        for (int i = 0; i < 4; i++) {
            int idx = tid + i * 256;             // 0..1023
            cp_async16(st + FOFF_KHI + idx * 16, kh + idx * 4);
            cp_async16(st + FOFF_KLO + idx * 16, kl + idx * 4);
        }
#pragma unroll
        for (int i = 0; i < 2; i++) {
            int idx = tid + i * 256;             // 0..511
            cp_async16(st + FOFF_VHI + idx * 16, vh + idx * 4);
            cp_async16(st + FOFF_VLO + idx * 16, vl + idx * 4);
        }
        CP_COMMIT();
    };
    issue_stage(0);

    float o[8][4];
#pragma unroll
    for (int n = 0; n < 8; n++)
#pragma unroll
        for (int k = 0; k < 4; k++) o[n][k] = 0.f;
    float m0 = -1e30f, m1 = -1e30f, l0 = 0.f, l1 = 0.f;

    for (int t = 0; t < 32; t++) {
        CP_WAIT0();
        __syncthreads();
        if (t + 1 < 32) issue_stage(t + 1);
        const uint32_t st = sbase + FOFF_ST + (t & 1) * FSTAGE;

        // ---- S = Q K^T  (3xTF32) ----
        float sf[8][4];
#pragma unroll
        for (int n = 0; n < 8; n++)
#pragma unroll
            for (int k = 0; k < 4; k++) sf[n][k] = 0.f;
#pragma unroll
        for (int ks = 0; ks < 8; ks++) {
            uint4 qa = *(const uint4*)(smraw + FOFF_QHI + ((ks * 8 + wid) * 32 + lane) * 16);
            uint4 ql = *(const uint4*)(smraw + FOFF_QLO + ((ks * 8 + wid) * 32 + lane) * 16);
            uint32_t ah[4] = {qa.x, qa.y, qa.z, qa.w};
            uint32_t al[4] = {ql.x, ql.y, ql.z, ql.w};
#pragma unroll
            for (int n = 0; n < 8; n++) {
                uint2 bh2 = *(const uint2*)(smraw + (st - sbase) + FOFF_KHI +
                                            ((ks * 8 + n) * 32 + lane) * 8);
                uint2 bl2 = *(const uint2*)(smraw + (st - sbase) + FOFF_KLO +
                                            ((ks * 8 + n) * 32 + lane) * 8);
                uint32_t bh[2] = {bh2.x, bh2.y};
                uint32_t bl[2] = {bl2.x, bl2.y};
                mma_tf32(sf[n], ah, bh);
                mma_tf32(sf[n], ah, bl);
                mma_tf32(sf[n], al, bh);
            }
        }

        // ---- online softmax on C-fragments (rows g and g+8 of this warp's 16) ----
        float mx0 = -1e30f, mx1 = -1e30f;
#pragma unroll
        for (int n = 0; n < 8; n++) {
            mx0 = fmaxf(mx0, fmaxf(sf[n][0], sf[n][1]));
            mx1 = fmaxf(mx1, fmaxf(sf[n][2], sf[n][3]));
        }
        mx0 = fmaxf(mx0, __shfl_xor_sync(0xffffffffu, mx0, 1));
        mx0 = fmaxf(mx0, __shfl_xor_sync(0xffffffffu, mx0, 2));
        mx1 = fmaxf(mx1, __shfl_xor_sync(0xffffffffu, mx1, 1));
        mx1 = fmaxf(mx1, __shfl_xor_sync(0xffffffffu, mx1, 2));
        float mn0 = fmaxf(m0, mx0), mn1 = fmaxf(m1, mx1);
        float al0 = __expf(m0 - mn0), al1 = __expf(m1 - mn1);
        float ls0 = 0.f, ls1 = 0.f;
#pragma unroll
        for (int n = 0; n < 8; n++) {
            sf[n][0] = __expf(sf[n][0] - mn0); ls0 += sf[n][0];
            sf[n][1] = __expf(sf[n][1] - mn0); ls0 += sf[n][1];
            sf[n][2] = __expf(sf[n][2] - mn1); ls1 += sf[n][2];
            sf[n][3] = __expf(sf[n][3] - mn1); ls1 += sf[n][3];
        }
        ls0 += __shfl_xor_sync(0xffffffffu, ls0, 1);
        ls0 += __shfl_xor_sync(0xffffffffu, ls0, 2);
        ls1 += __shfl_xor_sync(0xffffffffu, ls1, 1);
        ls1 += __shfl_xor_sync(0xffffffffu, ls1, 2);
        l0 = l0 * al0 + ls0; m0 = mn0;
        l1 = l1 * al1 + ls1; m1 = mn1;
#pragma unroll
        for (int n = 0; n < 8; n++) {
            o[n][0] *= al0; o[n][1] *= al0; o[n][2] *= al1; o[n][3] *= al1;
        }

        // ---- O += P V  (bf16, 2-limb P x 2-limb V, 3 passes) ----
#pragma unroll
        for (int j = 0; j < 4; j++) {
            float p00 = sf[2 * j][0], p01 = sf[2 * j][1];
            float p10 = sf[2 * j][2], p11 = sf[2 * j][3];
            float p20 = sf[2 * j + 1][0], p21 = sf[2 * j + 1][1];
            float p30 = sf[2 * j + 1][2], p31 = sf[2 * j + 1][3];
            uint32_t ahp[4], alp[4];
            ahp[0] = pack_bf16x2(p00, p01);
            ahp[1] = pack_bf16x2(p10, p11);
            ahp[2] = pack_bf16x2(p20, p21);
            ahp[3] = pack_bf16x2(p30, p31);
            alp[0] = pack_bf16x2(p00 - __bfloat162float(__float2bfloat16(p00)),
                                 p01 - __bfloat162float(__float2bfloat16(p01)));
            alp[1] = pack_bf16x2(p10 - __bfloat162float(__float2bfloat16(p10)),
                                 p11 - __bfloat162float(__float2bfloat16(p11)));
            alp[2] = pack_bf16x2(p20 - __bfloat162float(__float2bfloat16(p20)),
                                 p21 - __bfloat162float(__float2bfloat16(p21)));
            alp[3] = pack_bf16x2(p30 - __bfloat162float(__float2bfloat16(p30)),
                                 p31 - __bfloat162float(__float2bfloat16(p31)));
#pragma unroll
            for (int n = 0; n < 8; n++) {
                uint2 bh2 = *(const uint2*)(smraw + (st - sbase) + FOFF_VHI +
                                            ((j * 8 + n) * 32 + lane) * 8);
                uint2 bl2 = *(const uint2*)(smraw + (st - sbase) + FOFF_VLO +
                                            ((j * 8 + n) * 32 + lane) * 8);
                uint32_t bh[2] = {bh2.x, bh2.y};
                uint32_t bl[2] = {bl2.x, bl2.y};
                mma_bf16(o[n], ahp, bh);
                mma_bf16(o[n], alp, bh);
                mma_bf16(o[n], ahp, bl);
            }
        }
    }

    float inv0 = 1.f / l0, inv1 = 1.f / l1;
    float* Og = g_ab + (size_t)(b * SQ + qt * 128 + wid * 16) * DM + h * HD;
#pragma unroll
    for (int n = 0; n < 8; n++) {
        int c = n * 8 + 2 * tig;
        *(float2*)(Og + (size_t)g * DM + c) = make_float2(o[n][0] * inv0, o[n][1] * inv0);
        *(float2*)(Og + (size_t)(g + 8) * DM + c) = make_float2(o[n][2] * inv1, o[n][3] * inv1);
    }
}

// ================= launcher =================
extern "C" void kernel_launch(void* const* d_in, const int* in_sizes, int n_in,
                              void* d_out, int out_size) {
    (void)in_sizes; (void)n_in; (void)out_size;
    const float* query = (const float*)d_in[0];
    const float* key   = (const float*)d_in[1];
    const float* value = (const float*)d_in[2];
    const float* wq    = (const float*)d_in[3];
    const float* wk    = (const float*)d_in[4];
    const float* wv    = (const float*)d_in[5];
    const float* wo    = (const float*)d_in[6];
    float* out = (float*)d_out;

    float *pq, *pk, *pv, *pa;
    __nv_bfloat16 *ptw, *psp;
    cudaGetSymbolAddress((void**)&pq,  g_qb);
    cudaGetSymbolAddress((void**)&pk,  g_kb);
    cudaGetSymbolAddress((void**)&pv,  g_vb);
    cudaGetSymbolAddress((void**)&pa,  g_ab);
    cudaGetSymbolAddress((void**)&ptw, g_twb);
    cudaGetSymbolAddress((void**)&psp, g_split);

    const int smem_gemm  = 65536;
    const int smem_flash = 65536 + 2 * 49152;   // 163840
    cudaFuncSetAttribute(gemm_mma,   cudaFuncAttributeMaxDynamicSharedMemorySize, smem_gemm);
    cudaFuncSetAttribute(flash_mma2, cudaFuncAttributeMaxDynamicSharedMemorySize, smem_flash);

    absmean_partial<<<128, 256>>>(wq, wk, wv, wo);
    absmean_final<<<1, 4>>>();
    ternarize_k<<<(4 * DM * DM) / 256, 256>>>(wq, wk, wv, wo);

    dim3 gg(DM / 128, MTOT / 128);   // (8, 32)
    const int nf4 = MTOT * DM / 4;

    split3_k<<<nf4 / 256, 256>>>(query);
    gemm_mma<<<gg, 256, smem_gemm>>>(psp, ptw + 0 * (size_t)DM * DM, pq, 3072);
    qf_writer<<<dim3(16, 16, 2), 256>>>();

    split3_k<<<nf4 / 256, 256>>>(key);
    gemm_mma<<<gg, 256, smem_gemm>>>(psp, ptw + 1 * (size_t)DM * DM, pk, 3072);
    kf_writer<<<dim3(32, 16, 2), 256>>>();

    split2_k<<<nf4 / 256, 256>>>(value);
    gemm_mma<<<gg, 256, smem_gemm>>>(psp, ptw + 2 * (size_t)DM * DM, pv, 2048);
    vf_writer<<<dim3(32, 16, 2), 256>>>();

    flash_mma2<<<dim3(SQ / 128, NH, NB), 256, smem_flash>>>();

    split2_k<<<nf4 / 256, 256>>>(pa);
    gemm_mma<<<gg, 256, smem_gemm>>>(psp, ptw + 3 * (size_t)DM * DM, out, 2048);
}